// round 16
// baseline (speedup 1.0000x reference)
#include <cuda_runtime.h>
#include <cuda_bf16.h>
#include <math.h>

#define Bn 4
#define Qn 900
#define Kn 1024
#define En 256
#define Hn 8
#define QT 8
#define KT 32
#define NQT 113
#define NUNITS (Bn * NQT * 32)
#define NCTA 296
#define SCALE_Q 0.17677669529663687f
#define MASK_NEG (-10000.0f)

typedef unsigned long long ull;

__device__ __forceinline__ ull pk2(float lo, float hi) {
    ull r; asm("mov.b64 %0, {%1,%2};" : "=l"(r) : "f"(lo), "f"(hi)); return r;
}
__device__ __forceinline__ void upk2(ull v, float& lo, float& hi) {
    asm("mov.b64 {%0,%1}, %2;" : "=f"(lo), "=f"(hi) : "l"(v));
}
__device__ __forceinline__ ull fma2(ull a, ull b, ull c) {
    ull r; asm("fma.rn.f32x2 %0, %1, %2, %3;" : "=l"(r) : "l"(a), "l"(b), "l"(c)); return r;
}
__device__ __forceinline__ unsigned f2tf(float f) {
    unsigned r; asm("cvt.rna.tf32.f32 %0, %1;" : "=r"(r) : "f"(f)); return r;
}
__device__ __forceinline__ void mma_tf32(float c[4],
    unsigned a0, unsigned a1, unsigned a2, unsigned a3, unsigned b0, unsigned b1)
{
    asm volatile("mma.sync.aligned.m16n8k8.row.col.f32.tf32.tf32.f32 "
        "{%0,%1,%2,%3}, {%4,%5,%6,%7}, {%8,%9}, {%0,%1,%2,%3};"
        : "+f"(c[0]), "+f"(c[1]), "+f"(c[2]), "+f"(c[3])
        : "r"(a0), "r"(a1), "r"(a2), "r"(a3), "r"(b0), "r"(b1));
}
__device__ __forceinline__ void ldsm4(unsigned& r0, unsigned& r1,
                                      unsigned& r2, unsigned& r3, unsigned addr)
{
    asm volatile("ldmatrix.sync.aligned.m8n8.x4.shared.b16 {%0,%1,%2,%3}, [%4];"
                 : "=r"(r0), "=r"(r1), "=r"(r2), "=r"(r3) : "r"(addr));
}
__device__ __forceinline__ void cpa16(unsigned int dst, const void* src) {
    asm volatile("cp.async.cg.shared.global [%0], [%1], 16;" :: "r"(dst), "l"(src));
}
#define CP_COMMIT() asm volatile("cp.async.commit_group;")
#define CP_WAIT0()  asm volatile("cp.async.wait_group 0;" ::: "memory")
#define CP_WAIT1()  asm volatile("cp.async.wait_group 1;" ::: "memory")

__device__ __align__(16) float g_q[Bn * Qn * En];
__device__ __align__(16) float g_k[Bn * Kn * En];
__device__ __align__(16) float g_v[Bn * Kn * En];
__device__ __align__(16) float g_att[Bn * Qn * En];
__device__ __align__(16) float g_l[Bn * Qn * Hn];

// ---- qkv projection GEMM: 128x64 tile, 8x4 micro ----
__device__ __forceinline__ void proj_body(
    float (*As)[16][132], float (*Bs)[16][68],
    const float* __restrict__ A, const float* __restrict__ W,
    const float* __restrict__ bias, float* __restrict__ C, int M, float scale)
{
    const int m0 = blockIdx.x * 128;
    if (m0 >= M) return;
    const int n0 = blockIdx.y * 64;
    const int t = threadIdx.x;
    const int tx = t & 15, ty = t >> 4, ar = t >> 2, kc = (t & 3) * 4;

    ull acc2[8][2];
#pragma unroll
    for (int i = 0; i < 8; i++) { acc2[i][0] = 0ULL; acc2[i][1] = 0ULL; }
    const bool aok0 = (m0 + ar) < M, aok1 = (m0 + ar + 64) < M;

    float4 a0p = make_float4(0.f,0.f,0.f,0.f), a1p = a0p, b0p;
    if (aok0) a0p = *(const float4*)&A[(size_t)(m0 + ar) * 256 + kc];
    if (aok1) a1p = *(const float4*)&A[(size_t)(m0 + ar + 64) * 256 + kc];
    b0p = *(const float4*)&W[(size_t)(n0 + ar) * 256 + kc];
    {
        const float *a0f = (const float*)&a0p, *a1f = (const float*)&a1p, *b0f = (const float*)&b0p;
#pragma unroll
        for (int j = 0; j < 4; j++) {
            As[0][kc + j][ar] = a0f[j]; As[0][kc + j][ar + 64] = a1f[j]; Bs[0][kc + j][ar] = b0f[j];
        }
    }
    __syncthreads();

    for (int c = 0; c < 16; c++) {
        const int cur = c & 1;
        if (c < 15) {
            const int k1 = (c + 1) * 16;
            a0p = make_float4(0.f,0.f,0.f,0.f); a1p = a0p;
            if (aok0) a0p = *(const float4*)&A[(size_t)(m0 + ar) * 256 + k1 + kc];
            if (aok1) a1p = *(const float4*)&A[(size_t)(m0 + ar + 64) * 256 + k1 + kc];
            b0p = *(const float4*)&W[(size_t)(n0 + ar) * 256 + k1 + kc];
        }
#pragma unroll
        for (int kk = 0; kk < 16; kk++) {
            float4 av0 = *(const float4*)&As[cur][kk][ty * 8];
            float4 av1 = *(const float4*)&As[cur][kk][ty * 8 + 4];
            float4 bv  = *(const float4*)&Bs[cur][kk][tx * 4];
            ull b01 = pk2(bv.x, bv.y), b23 = pk2(bv.z, bv.w);
            float am[8] = {av0.x, av0.y, av0.z, av0.w, av1.x, av1.y, av1.z, av1.w};
#pragma unroll
            for (int i = 0; i < 8; i++) {
                ull ad = pk2(am[i], am[i]);
                acc2[i][0] = fma2(b01, ad, acc2[i][0]);
                acc2[i][1] = fma2(b23, ad, acc2[i][1]);
            }
        }
        if (c < 15) {
            const int nxt = cur ^ 1;
            const float *a0f = (const float*)&a0p, *a1f = (const float*)&a1p, *b0f = (const float*)&b0p;
#pragma unroll
            for (int j = 0; j < 4; j++) {
                As[nxt][kc + j][ar] = a0f[j]; As[nxt][kc + j][ar + 64] = a1f[j]; Bs[nxt][kc + j][ar] = b0f[j];
            }
            __syncthreads();
        }
    }
    const int n = n0 + tx * 4;
    const float4 bi = *(const float4*)&bias[n];
#pragma unroll
    for (int i = 0; i < 8; i++) {
        int m = m0 + ty * 8 + i;
        if (m < M) {
            float c0, c1, c2, c3;
            upk2(acc2[i][0], c0, c1); upk2(acc2[i][1], c2, c3);
            float4 o;
            o.x = scale * (c0 + bi.x); o.y = scale * (c1 + bi.y);
            o.z = scale * (c2 + bi.z); o.w = scale * (c3 + bi.w);
            *(float4*)&C[(size_t)m * 256 + n] = o;
        }
    }
}

__global__ __launch_bounds__(256) void proj3_kernel(
    const float* __restrict__ nodes, const float* __restrict__ images,
    const float* __restrict__ Wq,  const float* __restrict__ bq,
    const float* __restrict__ Wkv, const float* __restrict__ bkv,
    float* __restrict__ pq, float* __restrict__ pk, float* __restrict__ pv)
{
    if (blockIdx.z == 3) {   // zero O/l accumulators (hides under the GEMM slices)
        int id = (blockIdx.y * gridDim.x + blockIdx.x) * 256 + threadIdx.x; // 32768
        float4 z4 = make_float4(0.f, 0.f, 0.f, 0.f);
        for (int i = id; i < (Bn * Qn * En) / 4; i += 32768) ((float4*)g_att)[i] = z4;
        for (int i = id; i < Bn * Qn * Hn; i += 32768) g_l[i] = 0.f;
        return;
    }
    __shared__ __align__(16) float As[2][16][132];
    __shared__ __align__(16) float Bs[2][16][68];
    if (blockIdx.z == 0)      proj_body(As, Bs, nodes,  Wq,              bq,        pq, Bn * Qn, SCALE_Q);
    else if (blockIdx.z == 1) proj_body(As, Bs, images, Wkv,             bkv,       pk, Bn * Kn, 1.f);
    else                      proj_body(As, Bs, images, Wkv + 256 * 256, bkv + 256, pv, Bn * Kn, 1.f);
}

// ---- output projection: 128x64 tile, 8x4 micro, norm fused into A-loader ----
__global__ __launch_bounds__(256) void projo_kernel(
    const float* __restrict__ W, const float* __restrict__ bias, float* __restrict__ C)
{
    __shared__ __align__(16) float As[2][16][132];
    __shared__ __align__(16) float Bs[2][16][68];
    const int M = Bn * Qn;
    const int m0 = blockIdx.x * 128;
    if (m0 >= M) return;
    const int n0 = blockIdx.y * 64;
    const int t = threadIdx.x;
    const int tx = t & 15, ty = t >> 4, ar = t >> 2, kc = (t & 3) * 4;

    ull acc2[8][2];
#pragma unroll
    for (int i = 0; i < 8; i++) { acc2[i][0] = 0ULL; acc2[i][1] = 0ULL; }
    const int  r0 = m0 + ar, r1 = m0 + ar + 64;
    const bool aok0 = r0 < M, aok1 = r1 < M;

    // chunk c covers k in [16c,16c+16); head = c>>1 (never crosses a 32-dim boundary)
    float4 a0p = make_float4(0.f,0.f,0.f,0.f), a1p = a0p, b0p;
    if (aok0) {
        float inv = 1.f / g_l[r0 * Hn];
        a0p = *(const float4*)&g_att[(size_t)r0 * 256 + kc];
        a0p.x *= inv; a0p.y *= inv; a0p.z *= inv; a0p.w *= inv;
    }
    if (aok1) {
        float inv = 1.f / g_l[r1 * Hn];
        a1p = *(const float4*)&g_att[(size_t)r1 * 256 + kc];
        a1p.x *= inv; a1p.y *= inv; a1p.z *= inv; a1p.w *= inv;
    }
    b0p = *(const float4*)&W[(size_t)(n0 + ar) * 256 + kc];
    {
        const float *a0f = (const float*)&a0p, *a1f = (const float*)&a1p, *b0f = (const float*)&b0p;
#pragma unroll
        for (int j = 0; j < 4; j++) {
            As[0][kc + j][ar] = a0f[j]; As[0][kc + j][ar + 64] = a1f[j]; Bs[0][kc + j][ar] = b0f[j];
        }
    }
    __syncthreads();

    for (int c = 0; c < 16; c++) {
        const int cur = c & 1;
        if (c < 15) {
            const int k1 = (c + 1) * 16;
            const int hd = (c + 1) >> 1;
            a0p = make_float4(0.f,0.f,0.f,0.f); a1p = a0p;
            if (aok0) {
                float inv = 1.f / g_l[r0 * Hn + hd];
                a0p = *(const float4*)&g_att[(size_t)r0 * 256 + k1 + kc];
                a0p.x *= inv; a0p.y *= inv; a0p.z *= inv; a0p.w *= inv;
            }
            if (aok1) {
                float inv = 1.f / g_l[r1 * Hn + hd];
                a1p = *(const float4*)&g_att[(size_t)r1 * 256 + k1 + kc];
                a1p.x *= inv; a1p.y *= inv; a1p.z *= inv; a1p.w *= inv;
            }
            b0p = *(const float4*)&W[(size_t)(n0 + ar) * 256 + k1 + kc];
        }
#pragma unroll
        for (int kk = 0; kk < 16; kk++) {
            float4 av0 = *(const float4*)&As[cur][kk][ty * 8];
            float4 av1 = *(const float4*)&As[cur][kk][ty * 8 + 4];
            float4 bv  = *(const float4*)&Bs[cur][kk][tx * 4];
            ull b01 = pk2(bv.x, bv.y), b23 = pk2(bv.z, bv.w);
            float am[8] = {av0.x, av0.y, av0.z, av0.w, av1.x, av1.y, av1.z, av1.w};
#pragma unroll
            for (int i = 0; i < 8; i++) {
                ull ad = pk2(am[i], am[i]);
                acc2[i][0] = fma2(b01, ad, acc2[i][0]);
                acc2[i][1] = fma2(b23, ad, acc2[i][1]);
            }
        }
        if (c < 15) {
            const int nxt = cur ^ 1;
            const float *a0f = (const float*)&a0p, *a1f = (const float*)&a1p, *b0f = (const float*)&b0p;
#pragma unroll
            for (int j = 0; j < 4; j++) {
                As[nxt][kc + j][ar] = a0f[j]; As[nxt][kc + j][ar + 64] = a1f[j]; Bs[nxt][kc + j][ar] = b0f[j];
            }
            __syncthreads();
        }
    }
    const int n = n0 + tx * 4;
    const float4 bi = *(const float4*)&bias[n];
#pragma unroll
    for (int i = 0; i < 8; i++) {
        int m = m0 + ty * 8 + i;
        if (m < M) {
            float c0, c1, c2, c3;
            upk2(acc2[i][0], c0, c1); upk2(acc2[i][1], c2, c3);
            *(float4*)&C[(size_t)m * 256 + n] =
                make_float4(c0 + bi.x, c1 + bi.y, c2 + bi.z, c3 + bi.w);
        }
    }
}

// ---- attention: balanced contiguous (qtile,ktile) units, atomic merge ----
#define SM_K     0
#define SM_V     8320
#define SM_CPB0  16768
#define SM_CPB1  19072
#define SM_W1    21376
#define SM_BYTES (21632 * 4)

__device__ __forceinline__ void cpb_tile(
    float* __restrict__ dst, const float4* __restrict__ w1,
    const unsigned* __restrict__ bf0, const unsigned* __restrict__ bf1,
    float bias0, float bias1,
    const float* dxr, const float* dyr, const float* mr, int lane, int wq)
{
    float c0[4], c1[4];
    c0[0] = c0[2] = bias0; c0[1] = c0[3] = bias1;
    c1[0] = c1[2] = bias0; c1[1] = c1[3] = bias1;
#pragma unroll
    for (int s = 0; s < 8; s++) {
        float4 wA = w1[s * 8 + (lane & 3)];
        float4 wB = w1[s * 8 + 4 + (lane & 3)];
        unsigned b0 = bf0[s], b1 = bf1[s];
#pragma unroll
        for (int mt = 0; mt < 2; mt++) {
            float h00 = fmaxf(fmaf(wA.x, dxr[2*mt],   fmaf(wA.y, dyr[2*mt],   wA.z)), 0.f);
            float h10 = fmaxf(fmaf(wA.x, dxr[2*mt+1], fmaf(wA.y, dyr[2*mt+1], wA.z)), 0.f);
            float h01 = fmaxf(fmaf(wB.x, dxr[2*mt],   fmaf(wB.y, dyr[2*mt],   wB.z)), 0.f);
            float h11 = fmaxf(fmaf(wB.x, dxr[2*mt+1], fmaf(wB.y, dyr[2*mt+1], wB.z)), 0.f);
            float* cc = mt ? c1 : c0;
            mma_tf32(cc, __float_as_uint(h00), __float_as_uint(h10),
                         __float_as_uint(h01), __float_as_uint(h11), b0, b1);
        }
    }
    const int kswz = 8 * (lane & 3);
    const int h0 = 2 * (lane & 3), h1 = h0 + 1;
#pragma unroll
    for (int mt = 0; mt < 2; mt++) {
        float* cc = mt ? c1 : c0;
        int key0 = (lane >> 2) + 16 * mt, key1 = key0 + 8;
        dst[(h0 * 8 + wq) * 36 + (key0 ^ kswz)] = cc[0] + mr[2*mt];
        dst[(h1 * 8 + wq) * 36 + (key0 ^ kswz)] = cc[1] + mr[2*mt];
        dst[(h0 * 8 + wq) * 36 + (key1 ^ kswz)] = cc[2] + mr[2*mt+1];
        dst[(h1 * 8 + wq) * 36 + (key1 ^ kswz)] = cc[3] + mr[2*mt+1];
    }
}

__global__ __launch_bounds__(256, 2) void attn_kernel(
    const float* __restrict__ rd, const unsigned char* __restrict__ mask,
    const float* __restrict__ Wc1, const float* __restrict__ bc1,
    const float* __restrict__ Wc2, const float* __restrict__ bc2)
{
    extern __shared__ __align__(16) float sm[];
    float4* w1 = (float4*)(sm + SM_W1);
    const int t = threadIdx.x;
    const unsigned smem_u32 = (unsigned)__cvta_generic_to_shared(sm);
    const int wh = t >> 5, lane = t & 31;

    if (t < 64) w1[t] = make_float4(Wc1[2 * t], Wc1[2 * t + 1], bc1[t], 0.f);
    unsigned bf0[8], bf1[8];
    {
        const int hd = lane >> 2, jc = lane & 3;
#pragma unroll
        for (int s = 0; s < 8; s++) {
            bf0[s] = f2tf(Wc2[hd * 64 + s * 8 + jc]);
            bf1[s] = f2tf(Wc2[hd * 64 + s * 8 + 4 + jc]);
        }
    }
    const float bias0 = bc2[2 * (lane & 3)], bias1 = bc2[2 * (lane & 3) + 1];
    const int kswz = 8 * ((wh >> 1) & 3);
    const unsigned kbase = smem_u32 +
        (unsigned)((SM_K + (lane & 15) * 260 + wh * 32) * 4) + ((lane >> 4) * 16);
    __syncthreads();

    int u = (int)(((long long)blockIdx.x * NUNITS) / NCTA);
    const int u_end = (int)(((long long)(blockIdx.x + 1) * NUNITS) / NCTA);

    while (u < u_end) {
        const int bq = u >> 5, b = bq / NQT, qt = bq - b * NQT;
        const int q0 = qt * QT;
        const int kt_lo = u & 31;
        int nk = 32 - kt_lo;
        if (nk > u_end - u) nk = u_end - u;
        const int kt_hi = kt_lo + nk;
        u += nk;

        unsigned qb0[4], qb1[4];
        {
            const int ql = lane >> 2;
            const bool qv = (q0 + ql) < Qn;
            const float* qrow = &g_q[(size_t)((b * Qn) + (qv ? q0 + ql : 0)) * En + wh * 32];
#pragma unroll
            for (int kst = 0; kst < 4; kst++) {
                qb0[kst] = f2tf(qv ? qrow[kst * 8 + (lane & 3)]     : 0.f);
                qb1[kst] = f2tf(qv ? qrow[kst * 8 + 4 + (lane & 3)] : 0.f);
            }
        }
        const int qg1 = q0 + wh;
        const size_t rd_row = ((size_t)b * Qn + (qg1 < Qn ? qg1 : Qn - 1)) * Kn;

        {
            const int k0 = kt_lo * KT;
#pragma unroll
            for (int i = 0; i < 8; i++) {
                int idx = t + i * 256, kk = idx >> 6, e4 = idx & 63;
                size_t gidx = (size_t)((b * Kn) + (k0 + kk)) * En + e4 * 4;
                cpa16(smem_u32 + (SM_K + kk * 260 + e4 * 4) * 4, &g_k[gidx]);
                cpa16(smem_u32 + (SM_V + kk * 264 + e4 * 4) * 4, &g_v[gidx]);
            }
            CP_COMMIT();
            float dxr[4], dyr[4], mr[4];
#pragma unroll
            for (int g = 0; g < 4; g++) {
                int kr = k0 + (lane >> 2) + 8 * g;
                float2 r2 = *(const float2*)&rd[(rd_row + kr) * 2];
                dxr[g] = r2.x; dyr[g] = r2.y;
                mr[g] = mask[b * Kn + kr] ? MASK_NEG : 0.f;
            }
            cpb_tile(sm + SM_CPB0, w1, bf0, bf1, bias0, bias1, dxr, dyr, mr, lane, wh);
            CP_WAIT0();
            __syncthreads();
        }

        float l0 = 0.f, l1 = 0.f;
        float oc0[4] = {0.f,0.f,0.f,0.f}, oc1[4] = {0.f,0.f,0.f,0.f};

        for (int it = kt_lo; it < kt_hi; it++) {
            const int j = it - kt_lo, k0 = it * KT;
            float* cpb_cur = sm + ((j & 1) ? SM_CPB1 : SM_CPB0);
            float* cpb_nxt = sm + ((j & 1) ? SM_CPB0 : SM_CPB1);
            const bool more = (it + 1 < kt_hi);

            float dxr[4], dyr[4], mr[4];
            if (more) {
#pragma unroll
                for (int g = 0; g < 4; g++) {
                    int kr = k0 + KT + (lane >> 2) + 8 * g;
                    float2 r2 = *(const float2*)&rd[(rd_row + kr) * 2];
                    dxr[g] = r2.x; dyr[g] = r2.y;
                    mr[g] = mask[b * Kn + kr] ? MASK_NEG : 0.f;
                }
            }

            {
                float cQK[2][4] = {{0.f,0.f,0.f,0.f},{0.f,0.f,0.f,0.f}};
#pragma unroll
                for (int mt = 0; mt < 2; mt++)
#pragma unroll
                    for (int kst = 0; kst < 4; kst++) {
                        unsigned a0, a1, a2, a3;
                        ldsm4(a0, a1, a2, a3, kbase + mt * (16 * 260 * 4) + kst * 32);
                        mma_tf32(cQK[mt], a0, a1, a2, a3, qb0[kst], qb1[kst]);
                    }
                const int qc = 2 * (lane & 3);
#pragma unroll
                for (int mt = 0; mt < 2; mt++) {
                    int key0 = (lane >> 2) + 16 * mt, key1 = key0 + 8;
                    int r0 = (wh * 8 + qc) * 36, r1 = (wh * 8 + qc + 1) * 36;
                    float p0 = __expf(cQK[mt][0] + cpb_cur[r0 + (key0 ^ kswz)]);
                    float p1 = __expf(cQK[mt][1] + cpb_cur[r1 + (key0 ^ kswz)]);
                    float p2 = __expf(cQK[mt][2] + cpb_cur[r0 + (key1 ^ kswz)]);
                    float p3 = __expf(cQK[mt][3] + cpb_cur[r1 + (key1 ^ kswz)]);
                    cpb_cur[r0 + (key0 ^ kswz)] = p0;
                    cpb_cur[r1 + (key0 ^ kswz)] = p1;
                    cpb_cur[r0 + (key1 ^ kswz)] = p2;
                    cpb_cur[r1 + (key1 ^ kswz)] = p3;
                    l0 += p0 + p2; l1 += p1 + p3;
                }
            }
            CP_WAIT0();
            __syncthreads();

            if (more) {
#pragma unroll
                for (int i = 0; i < 8; i++) {
                    int idx = t + i * 256, kk = idx >> 6, e4 = idx & 63;
                    size_t gidx = (size_t)((b * Kn) + (k0 + KT + kk)) * En + e4 * 4;
                    cpa16(smem_u32 + (SM_K + kk * 260 + e4 * 4) * 4, &g_k[gidx]);
                }
                CP_COMMIT();
            }

            {
                unsigned pb0[4], pb1[4];
                const int prow = (wh * 8 + (lane >> 2)) * 36;
#pragma unroll
                for (int kst = 0; kst < 4; kst++) {
                    pb0[kst] = f2tf(cpb_cur[prow + ((kst * 8 + (lane & 3)) ^ kswz)]);
                    pb1[kst] = f2tf(cpb_cur[prow + ((kst * 8 + 4 + (lane & 3)) ^ kswz)]);
                }
                const float* vb = sm + SM_V + wh * 32;
#pragma unroll
                for (int dmt = 0; dmt < 2; dmt++) {
                    float* oc = dmt ? oc1 : oc0;
                    int d0 = (lane >> 2) + 16 * dmt, d1 = d0 + 8;
#pragma unroll
                    for (int kst = 0; kst < 4; kst++) {
                        int ka = kst * 8 + (lane & 3), kb = ka + 4;
                        mma_tf32(oc, f2tf(vb[ka * 264 + d0]), f2tf(vb[ka * 264 + d1]),
                                     f2tf(vb[kb * 264 + d0]), f2tf(vb[kb * 264 + d1]),
                                 pb0[kst], pb1[kst]);
                    }
                }
            }

            if (more)
                cpb_tile(cpb_nxt, w1, bf0, bf1, bias0, bias1, dxr, dyr, mr, lane, wh);
            __syncthreads();

            if (more) {
#pragma unroll
                for (int i = 0; i < 8; i++) {
                    int idx = t + i * 256, kk = idx >> 6, e4 = idx & 63;
                    size_t gidx = (size_t)((b * Kn) + (k0 + KT + kk)) * En + e4 * 4;
                    cpa16(smem_u32 + (SM_V + kk * 264 + e4 * 4) * 4, &g_v[gidx]);
                }
                CP_COMMIT();
                CP_WAIT1();
                __syncthreads();
            }
        }

        // segment epilogue: atomic merge of partial O and l
        {
#pragma unroll
            for (int off = 4; off < 32; off <<= 1) {
                l0 += __shfl_xor_sync(0xffffffffu, l0, off);
                l1 += __shfl_xor_sync(0xffffffffu, l1, off);
            }
            const int qc = 2 * (lane & 3);
            if ((lane >> 2) == 0) {
                if (q0 + qc < Qn)     atomicAdd(&g_l[((b * Qn) + q0 + qc) * Hn + wh], l0);
                if (q0 + qc + 1 < Qn) atomicAdd(&g_l[((b * Qn) + q0 + qc + 1) * Hn + wh], l1);
            }
            float* base0 = &g_att[(size_t)((b * Qn) + (q0 + qc)) * En + wh * 32];
            float* base1 = base0 + En;
#pragma unroll
            for (int dmt = 0; dmt < 2; dmt++) {
                float* oc = dmt ? oc1 : oc0;
                int d0 = (lane >> 2) + 16 * dmt;
                if (q0 + qc < Qn) {
                    atomicAdd(&base0[d0], oc[0]);
                    atomicAdd(&base0[d0 + 8], oc[2]);
                }
                if (q0 + qc + 1 < Qn) {
                    atomicAdd(&base1[d0], oc[1]);
                    atomicAdd(&base1[d0 + 8], oc[3]);
                }
            }
        }
    }
}

extern "C" void kernel_launch(void* const* d_in, const int* in_sizes, int n_in,
                              void* d_out, int out_size)
{
    const float*         nodes  = (const float*)d_in[0];
    const float*         images = (const float*)d_in[1];
    const unsigned char* imask  = (const unsigned char*)d_in[2];
    const float*         rd     = (const float*)d_in[3];
    const float*         Wq     = (const float*)d_in[4];
    const float*         bq     = (const float*)d_in[5];
    const float*         Wkv    = (const float*)d_in[6];
    const float*         bkv    = (const float*)d_in[7];
    const float*         Wc1    = (const float*)d_in[8];
    const float*         bc1    = (const float*)d_in[9];
    const float*         Wc2    = (const float*)d_in[10];
    const float*         bc2    = (const float*)d_in[11];
    const float*         Wo     = (const float*)d_in[12];
    const float*         bo     = (const float*)d_in[13];
    float*               out    = (float*)d_out;

    float *pq, *pk, *pv;
    cudaGetSymbolAddress((void**)&pq, g_q);
    cudaGetSymbolAddress((void**)&pk, g_k);
    cudaGetSymbolAddress((void**)&pv, g_v);

    {   // q/k/v projections + accumulator zeroing
        dim3 g(32, 4, 4);
        proj3_kernel<<<g, 256>>>(nodes, images, Wq, bq, Wkv, bkv, pq, pk, pv);
    }
    {   // balanced attention, atomic merge
        cudaFuncSetAttribute(attn_kernel,
                             cudaFuncAttributeMaxDynamicSharedMemorySize, SM_BYTES);
        attn_kernel<<<NCTA, 256, SM_BYTES>>>(rd, imask, Wc1, bc1, Wc2, bc2);
    }
    {   // output projection with fused normalization (128-row tiles, 116 CTAs)
        dim3 g(29, 4);
        projo_kernel<<<g, 256>>>(Wo, bo, out);
    }
}

// round 17
// speedup vs baseline: 1.0646x; 1.0646x over previous
#include <cuda_runtime.h>
#include <cuda_bf16.h>
#include <math.h>

#define Bn 4
#define Qn 900
#define Kn 1024
#define En 256
#define Hn 8
#define QT 8
#define KT 32
#define NQT 113
#define NUNITS (Bn * NQT * 32)
#define NCTA 296
#define SCALE_Q 0.17677669529663687f
#define MASK_NEG (-10000.0f)

typedef unsigned long long ull;

__device__ __forceinline__ ull pk2(float lo, float hi) {
    ull r; asm("mov.b64 %0, {%1,%2};" : "=l"(r) : "f"(lo), "f"(hi)); return r;
}
__device__ __forceinline__ void upk2(ull v, float& lo, float& hi) {
    asm("mov.b64 {%0,%1}, %2;" : "=f"(lo), "=f"(hi) : "l"(v));
}
__device__ __forceinline__ ull fma2(ull a, ull b, ull c) {
    ull r; asm("fma.rn.f32x2 %0, %1, %2, %3;" : "=l"(r) : "l"(a), "l"(b), "l"(c)); return r;
}
__device__ __forceinline__ unsigned f2tf(float f) {
    unsigned r; asm("cvt.rna.tf32.f32 %0, %1;" : "=r"(r) : "f"(f)); return r;
}
__device__ __forceinline__ void mma_tf32(float c[4],
    unsigned a0, unsigned a1, unsigned a2, unsigned a3, unsigned b0, unsigned b1)
{
    asm volatile("mma.sync.aligned.m16n8k8.row.col.f32.tf32.tf32.f32 "
        "{%0,%1,%2,%3}, {%4,%5,%6,%7}, {%8,%9}, {%0,%1,%2,%3};"
        : "+f"(c[0]), "+f"(c[1]), "+f"(c[2]), "+f"(c[3])
        : "r"(a0), "r"(a1), "r"(a2), "r"(a3), "r"(b0), "r"(b1));
}
__device__ __forceinline__ void ldsm4(unsigned& r0, unsigned& r1,
                                      unsigned& r2, unsigned& r3, unsigned addr)
{
    asm volatile("ldmatrix.sync.aligned.m8n8.x4.shared.b16 {%0,%1,%2,%3}, [%4];"
                 : "=r"(r0), "=r"(r1), "=r"(r2), "=r"(r3) : "r"(addr));
}
__device__ __forceinline__ void cpa16(unsigned int dst, const void* src) {
    asm volatile("cp.async.cg.shared.global [%0], [%1], 16;" :: "r"(dst), "l"(src));
}
#define CP_COMMIT() asm volatile("cp.async.commit_group;")
#define CP_WAIT0()  asm volatile("cp.async.wait_group 0;" ::: "memory")
#define CP_WAIT1()  asm volatile("cp.async.wait_group 1;" ::: "memory")

__device__ __align__(16) float g_q[Bn * Qn * En];
__device__ __align__(16) float g_k[Bn * Kn * En];
__device__ __align__(16) float g_v[Bn * Kn * En];
__device__ __align__(16) float g_att[Bn * Qn * En];
__device__ __align__(16) float g_l[Bn * Qn * Hn];

// ---- projection GEMM: 128x64 tile, 8x4 micro; optional tf32 pre-round of output ----
__device__ __forceinline__ void proj_body(
    float (*As)[16][132], float (*Bs)[16][68],
    const float* __restrict__ A, const float* __restrict__ W,
    const float* __restrict__ bias, float* __restrict__ C, int M, float scale,
    int round_tf)
{
    const int m0 = blockIdx.x * 128;
    if (m0 >= M) return;
    const int n0 = blockIdx.y * 64;
    const int t = threadIdx.x;
    const int tx = t & 15, ty = t >> 4, ar = t >> 2, kc = (t & 3) * 4;

    ull acc2[8][2];
#pragma unroll
    for (int i = 0; i < 8; i++) { acc2[i][0] = 0ULL; acc2[i][1] = 0ULL; }
    const bool aok0 = (m0 + ar) < M, aok1 = (m0 + ar + 64) < M;

    float4 a0p = make_float4(0.f,0.f,0.f,0.f), a1p = a0p, b0p;
    if (aok0) a0p = *(const float4*)&A[(size_t)(m0 + ar) * 256 + kc];
    if (aok1) a1p = *(const float4*)&A[(size_t)(m0 + ar + 64) * 256 + kc];
    b0p = *(const float4*)&W[(size_t)(n0 + ar) * 256 + kc];
    {
        const float *a0f = (const float*)&a0p, *a1f = (const float*)&a1p, *b0f = (const float*)&b0p;
#pragma unroll
        for (int j = 0; j < 4; j++) {
            As[0][kc + j][ar] = a0f[j]; As[0][kc + j][ar + 64] = a1f[j]; Bs[0][kc + j][ar] = b0f[j];
        }
    }
    __syncthreads();

    for (int c = 0; c < 16; c++) {
        const int cur = c & 1;
        if (c < 15) {
            const int k1 = (c + 1) * 16;
            a0p = make_float4(0.f,0.f,0.f,0.f); a1p = a0p;
            if (aok0) a0p = *(const float4*)&A[(size_t)(m0 + ar) * 256 + k1 + kc];
            if (aok1) a1p = *(const float4*)&A[(size_t)(m0 + ar + 64) * 256 + k1 + kc];
            b0p = *(const float4*)&W[(size_t)(n0 + ar) * 256 + k1 + kc];
        }
#pragma unroll
        for (int kk = 0; kk < 16; kk++) {
            float4 av0 = *(const float4*)&As[cur][kk][ty * 8];
            float4 av1 = *(const float4*)&As[cur][kk][ty * 8 + 4];
            float4 bv  = *(const float4*)&Bs[cur][kk][tx * 4];
            ull b01 = pk2(bv.x, bv.y), b23 = pk2(bv.z, bv.w);
            float am[8] = {av0.x, av0.y, av0.z, av0.w, av1.x, av1.y, av1.z, av1.w};
#pragma unroll
            for (int i = 0; i < 8; i++) {
                ull ad = pk2(am[i], am[i]);
                acc2[i][0] = fma2(b01, ad, acc2[i][0]);
                acc2[i][1] = fma2(b23, ad, acc2[i][1]);
            }
        }
        if (c < 15) {
            const int nxt = cur ^ 1;
            const float *a0f = (const float*)&a0p, *a1f = (const float*)&a1p, *b0f = (const float*)&b0p;
#pragma unroll
            for (int j = 0; j < 4; j++) {
                As[nxt][kc + j][ar] = a0f[j]; As[nxt][kc + j][ar + 64] = a1f[j]; Bs[nxt][kc + j][ar] = b0f[j];
            }
            __syncthreads();
        }
    }
    const int n = n0 + tx * 4;
    const float4 bi = *(const float4*)&bias[n];
#pragma unroll
    for (int i = 0; i < 8; i++) {
        int m = m0 + ty * 8 + i;
        if (m < M) {
            float c0, c1, c2, c3;
            upk2(acc2[i][0], c0, c1); upk2(acc2[i][1], c2, c3);
            float4 o;
            o.x = scale * (c0 + bi.x); o.y = scale * (c1 + bi.y);
            o.z = scale * (c2 + bi.z); o.w = scale * (c3 + bi.w);
            if (round_tf) {   // pre-round to tf32 so attn AV can use raw bits (bit-identical)
                o.x = __uint_as_float(f2tf(o.x)); o.y = __uint_as_float(f2tf(o.y));
                o.z = __uint_as_float(f2tf(o.z)); o.w = __uint_as_float(f2tf(o.w));
            }
            *(float4*)&C[(size_t)m * 256 + n] = o;
        }
    }
}

__global__ __launch_bounds__(256) void proj3_kernel(
    const float* __restrict__ nodes, const float* __restrict__ images,
    const float* __restrict__ Wq,  const float* __restrict__ bq,
    const float* __restrict__ Wkv, const float* __restrict__ bkv,
    float* __restrict__ pq, float* __restrict__ pk, float* __restrict__ pv)
{
    if (blockIdx.z == 3) {   // zero O/l accumulators (hides under the GEMM slices)
        int id = (blockIdx.y * gridDim.x + blockIdx.x) * 256 + threadIdx.x; // 32768
        float4 z4 = make_float4(0.f, 0.f, 0.f, 0.f);
        for (int i = id; i < (Bn * Qn * En) / 4; i += 32768) ((float4*)g_att)[i] = z4;
        for (int i = id; i < Bn * Qn * Hn; i += 32768) g_l[i] = 0.f;
        return;
    }
    __shared__ __align__(16) float As[2][16][132];
    __shared__ __align__(16) float Bs[2][16][68];
    if (blockIdx.z == 0)      proj_body(As, Bs, nodes,  Wq,              bq,        pq, Bn * Qn, SCALE_Q, 0);
    else if (blockIdx.z == 1) proj_body(As, Bs, images, Wkv,             bkv,       pk, Bn * Kn, 1.f, 0);
    else                      proj_body(As, Bs, images, Wkv + 256 * 256, bkv + 256, pv, Bn * Kn, 1.f, 1);
}

__global__ __launch_bounds__(256) void projo_kernel(
    const float* __restrict__ A, const float* __restrict__ W,
    const float* __restrict__ bias, float* __restrict__ C, int M)
{
    __shared__ __align__(16) float As[2][16][132];
    __shared__ __align__(16) float Bs[2][16][68];
    proj_body(As, Bs, A, W, bias, C, M, 1.f, 0);
}

__global__ __launch_bounds__(256) void norm_kernel() {
    int idx = blockIdx.x * 256 + threadIdx.x;          // 230400 float4
    int row = idx >> 6, head = (idx & 63) >> 3;
    float inv = 1.f / g_l[row * Hn + head];
    float4 v = ((float4*)g_att)[idx];
    v.x *= inv; v.y *= inv; v.z *= inv; v.w *= inv;
    ((float4*)g_att)[idx] = v;
}

// ---- attention: balanced contiguous (qtile,ktile) units, atomic merge ----
#define SM_K     0
#define SM_V     8320
#define SM_CPB0  16768
#define SM_CPB1  19072
#define SM_W1    21376
#define SM_BYTES (21632 * 4)

__device__ __forceinline__ void cpb_tile(
    float* __restrict__ dst, const float4* __restrict__ w1,
    const unsigned* __restrict__ bf0, const unsigned* __restrict__ bf1,
    float bias0, float bias1,
    const float* dxr, const float* dyr, const float* mr, int lane, int wq)
{
    float c0[4], c1[4];
    c0[0] = c0[2] = bias0; c0[1] = c0[3] = bias1;
    c1[0] = c1[2] = bias0; c1[1] = c1[3] = bias1;
#pragma unroll
    for (int s = 0; s < 8; s++) {
        float4 wA = w1[s * 8 + (lane & 3)];
        float4 wB = w1[s * 8 + 4 + (lane & 3)];
        unsigned b0 = bf0[s], b1 = bf1[s];
#pragma unroll
        for (int mt = 0; mt < 2; mt++) {
            float h00 = fmaxf(fmaf(wA.x, dxr[2*mt],   fmaf(wA.y, dyr[2*mt],   wA.z)), 0.f);
            float h10 = fmaxf(fmaf(wA.x, dxr[2*mt+1], fmaf(wA.y, dyr[2*mt+1], wA.z)), 0.f);
            float h01 = fmaxf(fmaf(wB.x, dxr[2*mt],   fmaf(wB.y, dyr[2*mt],   wB.z)), 0.f);
            float h11 = fmaxf(fmaf(wB.x, dxr[2*mt+1], fmaf(wB.y, dyr[2*mt+1], wB.z)), 0.f);
            float* cc = mt ? c1 : c0;
            mma_tf32(cc, __float_as_uint(h00), __float_as_uint(h10),
                         __float_as_uint(h01), __float_as_uint(h11), b0, b1);
        }
    }
    const int kswz = 8 * (lane & 3);
    const int h0 = 2 * (lane & 3), h1 = h0 + 1;
#pragma unroll
    for (int mt = 0; mt < 2; mt++) {
        float* cc = mt ? c1 : c0;
        int key0 = (lane >> 2) + 16 * mt, key1 = key0 + 8;
        dst[(h0 * 8 + wq) * 36 + (key0 ^ kswz)] = cc[0] + mr[2*mt];
        dst[(h1 * 8 + wq) * 36 + (key0 ^ kswz)] = cc[1] + mr[2*mt];
        dst[(h0 * 8 + wq) * 36 + (key1 ^ kswz)] = cc[2] + mr[2*mt+1];
        dst[(h1 * 8 + wq) * 36 + (key1 ^ kswz)] = cc[3] + mr[2*mt+1];
    }
}

__global__ __launch_bounds__(256, 2) void attn_kernel(
    const float* __restrict__ rd, const unsigned char* __restrict__ mask,
    const float* __restrict__ Wc1, const float* __restrict__ bc1,
    const float* __restrict__ Wc2, const float* __restrict__ bc2)
{
    extern __shared__ __align__(16) float sm[];
    float4* w1 = (float4*)(sm + SM_W1);
    const int t = threadIdx.x;
    const unsigned smem_u32 = (unsigned)__cvta_generic_to_shared(sm);
    const int wh = t >> 5, lane = t & 31;

    if (t < 64) w1[t] = make_float4(Wc1[2 * t], Wc1[2 * t + 1], bc1[t], 0.f);
    unsigned bf0[8], bf1[8];
    {
        const int hd = lane >> 2, jc = lane & 3;
#pragma unroll
        for (int s = 0; s < 8; s++) {
            bf0[s] = f2tf(Wc2[hd * 64 + s * 8 + jc]);
            bf1[s] = f2tf(Wc2[hd * 64 + s * 8 + 4 + jc]);
        }
    }
    const float bias0 = bc2[2 * (lane & 3)], bias1 = bc2[2 * (lane & 3) + 1];
    const int kswz = 8 * ((wh >> 1) & 3);
    const unsigned kbase = smem_u32 +
        (unsigned)((SM_K + (lane & 15) * 260 + wh * 32) * 4) + ((lane >> 4) * 16);
    __syncthreads();

    int u = (int)(((long long)blockIdx.x * NUNITS) / NCTA);
    const int u_end = (int)(((long long)(blockIdx.x + 1) * NUNITS) / NCTA);

    while (u < u_end) {
        const int bq = u >> 5, b = bq / NQT, qt = bq - b * NQT;
        const int q0 = qt * QT;
        const int kt_lo = u & 31;
        int nk = 32 - kt_lo;
        if (nk > u_end - u) nk = u_end - u;
        const int kt_hi = kt_lo + nk;
        u += nk;

        unsigned qb0[4], qb1[4];
        {
            const int ql = lane >> 2;
            const bool qv = (q0 + ql) < Qn;
            const float* qrow = &g_q[(size_t)((b * Qn) + (qv ? q0 + ql : 0)) * En + wh * 32];
#pragma unroll
            for (int kst = 0; kst < 4; kst++) {
                qb0[kst] = f2tf(qv ? qrow[kst * 8 + (lane & 3)]     : 0.f);
                qb1[kst] = f2tf(qv ? qrow[kst * 8 + 4 + (lane & 3)] : 0.f);
            }
        }
        const int qg1 = q0 + wh;
        const size_t rd_row = ((size_t)b * Qn + (qg1 < Qn ? qg1 : Qn - 1)) * Kn;

        {
            const int k0 = kt_lo * KT;
#pragma unroll
            for (int i = 0; i < 8; i++) {
                int idx = t + i * 256, kk = idx >> 6, e4 = idx & 63;
                size_t gidx = (size_t)((b * Kn) + (k0 + kk)) * En + e4 * 4;
                cpa16(smem_u32 + (SM_K + kk * 260 + e4 * 4) * 4, &g_k[gidx]);
                cpa16(smem_u32 + (SM_V + kk * 264 + e4 * 4) * 4, &g_v[gidx]);
            }
            CP_COMMIT();
            float dxr[4], dyr[4], mr[4];
#pragma unroll
            for (int g = 0; g < 4; g++) {
                int kr = k0 + (lane >> 2) + 8 * g;
                float2 r2 = *(const float2*)&rd[(rd_row + kr) * 2];
                dxr[g] = r2.x; dyr[g] = r2.y;
                mr[g] = mask[b * Kn + kr] ? MASK_NEG : 0.f;
            }
            cpb_tile(sm + SM_CPB0, w1, bf0, bf1, bias0, bias1, dxr, dyr, mr, lane, wh);
            CP_WAIT0();
            __syncthreads();
        }

        float l0 = 0.f, l1 = 0.f;
        float oc0[4] = {0.f,0.f,0.f,0.f}, oc1[4] = {0.f,0.f,0.f,0.f};

        for (int it = kt_lo; it < kt_hi; it++) {
            const int j = it - kt_lo, k0 = it * KT;
            float* cpb_cur = sm + ((j & 1) ? SM_CPB1 : SM_CPB0);
            float* cpb_nxt = sm + ((j & 1) ? SM_CPB0 : SM_CPB1);
            const bool more = (it + 1 < kt_hi);

            float dxr[4], dyr[4], mr[4];
            if (more) {
#pragma unroll
                for (int g = 0; g < 4; g++) {
                    int kr = k0 + KT + (lane >> 2) + 8 * g;
                    float2 r2 = *(const float2*)&rd[(rd_row + kr) * 2];
                    dxr[g] = r2.x; dyr[g] = r2.y;
                    mr[g] = mask[b * Kn + kr] ? MASK_NEG : 0.f;
                }
            }

            {
                float cQK[2][4] = {{0.f,0.f,0.f,0.f},{0.f,0.f,0.f,0.f}};
#pragma unroll
                for (int mt = 0; mt < 2; mt++)
#pragma unroll
                    for (int kst = 0; kst < 4; kst++) {
                        unsigned a0, a1, a2, a3;
                        ldsm4(a0, a1, a2, a3, kbase + mt * (16 * 260 * 4) + kst * 32);
                        mma_tf32(cQK[mt], a0, a1, a2, a3, qb0[kst], qb1[kst]);
                    }
                const int qc = 2 * (lane & 3);
#pragma unroll
                for (int mt = 0; mt < 2; mt++) {
                    int key0 = (lane >> 2) + 16 * mt, key1 = key0 + 8;
                    int r0 = (wh * 8 + qc) * 36, r1 = (wh * 8 + qc + 1) * 36;
                    float p0 = __expf(cQK[mt][0] + cpb_cur[r0 + (key0 ^ kswz)]);
                    float p1 = __expf(cQK[mt][1] + cpb_cur[r1 + (key0 ^ kswz)]);
                    float p2 = __expf(cQK[mt][2] + cpb_cur[r0 + (key1 ^ kswz)]);
                    float p3 = __expf(cQK[mt][3] + cpb_cur[r1 + (key1 ^ kswz)]);
                    cpb_cur[r0 + (key0 ^ kswz)] = p0;
                    cpb_cur[r1 + (key0 ^ kswz)] = p1;
                    cpb_cur[r0 + (key1 ^ kswz)] = p2;
                    cpb_cur[r1 + (key1 ^ kswz)] = p3;
                    l0 += p0 + p2; l1 += p1 + p3;
                }
            }
            CP_WAIT0();
            __syncthreads();

            if (more) {
#pragma unroll
                for (int i = 0; i < 8; i++) {
                    int idx = t + i * 256, kk = idx >> 6, e4 = idx & 63;
                    size_t gidx = (size_t)((b * Kn) + (k0 + KT + kk)) * En + e4 * 4;
                    cpa16(smem_u32 + (SM_K + kk * 260 + e4 * 4) * 4, &g_k[gidx]);
                }
                CP_COMMIT();
            }

            {   // AV: V is pre-rounded tf32 -> raw bits (bit-identical to f2tf per use)
                unsigned pb0[4], pb1[4];
                const int prow = (wh * 8 + (lane >> 2)) * 36;
#pragma unroll
                for (int kst = 0; kst < 4; kst++) {
                    pb0[kst] = f2tf(cpb_cur[prow + ((kst * 8 + (lane & 3)) ^ kswz)]);
                    pb1[kst] = f2tf(cpb_cur[prow + ((kst * 8 + 4 + (lane & 3)) ^ kswz)]);
                }
                const float* vb = sm + SM_V + wh * 32;
#pragma unroll
                for (int dmt = 0; dmt < 2; dmt++) {
                    float* oc = dmt ? oc1 : oc0;
                    int d0 = (lane >> 2) + 16 * dmt, d1 = d0 + 8;
#pragma unroll
                    for (int kst = 0; kst < 4; kst++) {
                        int ka = kst * 8 + (lane & 3), kb = ka + 4;
                        mma_tf32(oc,
                                 __float_as_uint(vb[ka * 264 + d0]),
                                 __float_as_uint(vb[ka * 264 + d1]),
                                 __float_as_uint(vb[kb * 264 + d0]),
                                 __float_as_uint(vb[kb * 264 + d1]),
                                 pb0[kst], pb1[kst]);
                    }
                }
            }

            if (more)
                cpb_tile(cpb_nxt, w1, bf0, bf1, bias0, bias1, dxr, dyr, mr, lane, wh);
            __syncthreads();

            if (more) {
#pragma unroll
                for (int i = 0; i < 8; i++) {
                    int idx = t + i * 256, kk = idx >> 6, e4 = idx & 63;
                    size_t gidx = (size_t)((b * Kn) + (k0 + KT + kk)) * En + e4 * 4;
                    cpa16(smem_u32 + (SM_V + kk * 264 + e4 * 4) * 4, &g_v[gidx]);
                }
                CP_COMMIT();
                CP_WAIT1();
                __syncthreads();
            }
        }

        // segment epilogue: atomic merge of partial O and l
        {
#pragma unroll
            for (int off = 4; off < 32; off <<= 1) {
                l0 += __shfl_xor_sync(0xffffffffu, l0, off);
                l1 += __shfl_xor_sync(0xffffffffu, l1, off);
            }
            const int qc = 2 * (lane & 3);
            if ((lane >> 2) == 0) {
                if (q0 + qc < Qn)     atomicAdd(&g_l[((b * Qn) + q0 + qc) * Hn + wh], l0);
                if (q0 + qc + 1 < Qn) atomicAdd(&g_l[((b * Qn) + q0 + qc + 1) * Hn + wh], l1);
            }
            float* base0 = &g_att[(size_t)((b * Qn) + (q0 + qc)) * En + wh * 32];
            float* base1 = base0 + En;
#pragma unroll
            for (int dmt = 0; dmt < 2; dmt++) {
                float* oc = dmt ? oc1 : oc0;
                int d0 = (lane >> 2) + 16 * dmt;
                if (q0 + qc < Qn) {
                    atomicAdd(&base0[d0], oc[0]);
                    atomicAdd(&base0[d0 + 8], oc[2]);
                }
                if (q0 + qc + 1 < Qn) {
                    atomicAdd(&base1[d0], oc[1]);
                    atomicAdd(&base1[d0 + 8], oc[3]);
                }
            }
        }
    }
}

extern "C" void kernel_launch(void* const* d_in, const int* in_sizes, int n_in,
                              void* d_out, int out_size)
{
    const float*         nodes  = (const float*)d_in[0];
    const float*         images = (const float*)d_in[1];
    const unsigned char* imask  = (const unsigned char*)d_in[2];
    const float*         rd     = (const float*)d_in[3];
    const float*         Wq     = (const float*)d_in[4];
    const float*         bq     = (const float*)d_in[5];
    const float*         Wkv    = (const float*)d_in[6];
    const float*         bkv    = (const float*)d_in[7];
    const float*         Wc1    = (const float*)d_in[8];
    const float*         bc1    = (const float*)d_in[9];
    const float*         Wc2    = (const float*)d_in[10];
    const float*         bc2    = (const float*)d_in[11];
    const float*         Wo     = (const float*)d_in[12];
    const float*         bo     = (const float*)d_in[13];
    float*               out    = (float*)d_out;

    float *pq, *pk, *pv, *pa;
    cudaGetSymbolAddress((void**)&pq, g_q);
    cudaGetSymbolAddress((void**)&pk, g_k);
    cudaGetSymbolAddress((void**)&pv, g_v);
    cudaGetSymbolAddress((void**)&pa, g_att);

    const int MQ = Bn * Qn;

    {   // q/k/v projections (V pre-rounded to tf32) + accumulator zeroing
        dim3 g(32, 4, 4);
        proj3_kernel<<<g, 256>>>(nodes, images, Wq, bq, Wkv, bkv, pq, pk, pv);
    }
    {   // balanced attention, atomic merge
        cudaFuncSetAttribute(attn_kernel,
                             cudaFuncAttributeMaxDynamicSharedMemorySize, SM_BYTES);
        attn_kernel<<<NCTA, 256, SM_BYTES>>>(rd, imask, Wc1, bc1, Wc2, bc2);
    }
    norm_kernel<<<900, 256>>>();
    {   // output projection (128-row tiles, as in the 228.1us best)
        dim3 g((MQ + 127) / 128, 4);
        projo_kernel<<<g, 256>>>(pa, Wo, bo, out, MQ);
    }
}